// round 1
// baseline (speedup 1.0000x reference)
#include <cuda_runtime.h>
#include <math.h>

#define BATCH 2
#define SEQ   2048
#define DIM   512
#define NH    8
#define BHN   (BATCH*NH)                 // 16
#define SCALE 0.04419417382415922f      // 1/sqrt(512)

// Scratch (device globals; no runtime allocation allowed)
#define BHSD 16777216ULL                  // BH*S*D
__device__ float g_qkv[50331648];         // [3][B][H][S][D]  (qh, kh, vh)
__device__ float g_scores[67108864];      // [B][H][S][S]  scores -> probs in place
__device__ float g_attn[16777216];        // [B][H][S][D]

// ---------------------------------------------------------------------------
// Kernel 1: per-head QKV projection, RoPE fused into epilogue for q/k.
// C[m,n] = sum_k q[m,k] * W[h][k,n];  m = b*S+s;  64x64 tile, 256 threads.
// ---------------------------------------------------------------------------
__global__ __launch_bounds__(256) void proj_kernel(
    const float* __restrict__ q, const float* __restrict__ Wq,
    const float* __restrict__ Wk, const float* __restrict__ Wv)
{
    __shared__ float As[64][33];
    __shared__ float Bs[32][64];

    const int t  = threadIdx.x;
    const int tx = t & 15, ty = t >> 4;
    const int n0 = blockIdx.x * 64;
    const int m0 = blockIdx.y * 64;
    const int z  = blockIdx.z;
    const int h = z / 3, which = z % 3;
    const float* W = (which == 0 ? Wq : (which == 1 ? Wk : Wv)) + (size_t)h * DIM * DIM;

    float acc[4][4];
#pragma unroll
    for (int i = 0; i < 4; i++)
#pragma unroll
        for (int j = 0; j < 4; j++) acc[i][j] = 0.f;

    const int la_r = t >> 3, la_c = (t & 7) * 4;     // A loader: 32 rows x 32 cols per rep
    const int lb_r = t >> 4, lb_c = (t & 15) * 4;    // B loader: 16 rows x 64 cols per rep

    for (int k0 = 0; k0 < DIM; k0 += 32) {
#pragma unroll
        for (int rep = 0; rep < 2; rep++) {
            int r = la_r + rep * 32;
            float4 v = *(const float4*)(q + (size_t)(m0 + r) * DIM + k0 + la_c);
            As[r][la_c + 0] = v.x; As[r][la_c + 1] = v.y;
            As[r][la_c + 2] = v.z; As[r][la_c + 3] = v.w;
        }
#pragma unroll
        for (int rep = 0; rep < 2; rep++) {
            int r = lb_r + rep * 16;
            float4 v = *(const float4*)(W + (size_t)(k0 + r) * DIM + n0 + lb_c);
            *(float4*)&Bs[r][lb_c] = v;
        }
        __syncthreads();
#pragma unroll
        for (int kk = 0; kk < 32; kk++) {
            float a0 = As[ty * 4 + 0][kk];
            float a1 = As[ty * 4 + 1][kk];
            float a2 = As[ty * 4 + 2][kk];
            float a3 = As[ty * 4 + 3][kk];
            float4 bv = *(float4*)&Bs[kk][tx * 4];
            acc[0][0] += a0 * bv.x; acc[0][1] += a0 * bv.y; acc[0][2] += a0 * bv.z; acc[0][3] += a0 * bv.w;
            acc[1][0] += a1 * bv.x; acc[1][1] += a1 * bv.y; acc[1][2] += a1 * bv.z; acc[1][3] += a1 * bv.w;
            acc[2][0] += a2 * bv.x; acc[2][1] += a2 * bv.y; acc[2][2] += a2 * bv.z; acc[2][3] += a2 * bv.w;
            acc[3][0] += a3 * bv.x; acc[3][1] += a3 * bv.y; acc[3][2] += a3 * bv.z; acc[3][3] += a3 * bv.w;
        }
        __syncthreads();
    }

#pragma unroll
    for (int i = 0; i < 4; i++) {
        int m = m0 + ty * 4 + i;
        int bb = m >> 11;          // m / S
        int s  = m & (SEQ - 1);
        float v0 = acc[i][0], v1 = acc[i][1], v2 = acc[i][2], v3 = acc[i][3];
        if (which < 2) {
            // RoPE: pairs (n, n+1) with angle s * 10000^{-n/DIM}, n even.
            int n = n0 + tx * 4;
            {
                float inv = 1.0f / powf(10000.0f, (float)n * (1.0f / DIM));
                float ang = (float)s * inv;
                float cs = cosf(ang), sn = sinf(ang);
                float x1 = v0, x2 = v1;
                v0 = x1 * cs - x2 * sn;
                v1 = x1 * sn + x2 * cs;
            }
            {
                float inv = 1.0f / powf(10000.0f, (float)(n + 2) * (1.0f / DIM));
                float ang = (float)s * inv;
                float cs = cosf(ang), sn = sinf(ang);
                float x1 = v2, x2 = v3;
                v2 = x1 * cs - x2 * sn;
                v3 = x1 * sn + x2 * cs;
            }
        }
        float4 o = make_float4(v0, v1, v2, v3);
        *(float4*)(g_qkv + (size_t)which * BHSD +
                   (((size_t)(bb * NH + h)) * SEQ + s) * DIM + n0 + tx * 4) = o;
    }
}

// ---------------------------------------------------------------------------
// Kernel 2: scores[q,k] = scale * dot(qh[q,:], kh[k,:]).  Skips kt > qt tiles.
// ---------------------------------------------------------------------------
__global__ __launch_bounds__(256) void scores_kernel()
{
    const int kt = blockIdx.x, qt = blockIdx.y, bh = blockIdx.z;
    if (kt > qt) return;

    __shared__ float As[64][33];
    __shared__ float Ks[64][33];

    const float* Q = g_qkv + (size_t)bh * SEQ * DIM;
    const float* K = g_qkv + BHSD + (size_t)bh * SEQ * DIM;
    float* Sc = g_scores + (size_t)bh * SEQ * SEQ;

    const int t = threadIdx.x, tx = t & 15, ty = t >> 4;
    const int q0 = qt * 64, k0v = kt * 64;
    const int lr = t >> 3, lc = (t & 7) * 4;

    float acc[4][4];
#pragma unroll
    for (int i = 0; i < 4; i++)
#pragma unroll
        for (int j = 0; j < 4; j++) acc[i][j] = 0.f;

    for (int d0 = 0; d0 < DIM; d0 += 32) {
#pragma unroll
        for (int rep = 0; rep < 2; rep++) {
            int r = lr + rep * 32;
            float4 v = *(const float4*)(Q + (size_t)(q0 + r) * DIM + d0 + lc);
            As[r][lc + 0] = v.x; As[r][lc + 1] = v.y; As[r][lc + 2] = v.z; As[r][lc + 3] = v.w;
            float4 w = *(const float4*)(K + (size_t)(k0v + r) * DIM + d0 + lc);
            Ks[r][lc + 0] = w.x; Ks[r][lc + 1] = w.y; Ks[r][lc + 2] = w.z; Ks[r][lc + 3] = w.w;
        }
        __syncthreads();
#pragma unroll
        for (int kk = 0; kk < 32; kk++) {
            float a0 = As[ty * 4 + 0][kk];
            float a1 = As[ty * 4 + 1][kk];
            float a2 = As[ty * 4 + 2][kk];
            float a3 = As[ty * 4 + 3][kk];
            float b0 = Ks[tx * 4 + 0][kk];
            float b1 = Ks[tx * 4 + 1][kk];
            float b2 = Ks[tx * 4 + 2][kk];
            float b3 = Ks[tx * 4 + 3][kk];
            acc[0][0] += a0 * b0; acc[0][1] += a0 * b1; acc[0][2] += a0 * b2; acc[0][3] += a0 * b3;
            acc[1][0] += a1 * b0; acc[1][1] += a1 * b1; acc[1][2] += a1 * b2; acc[1][3] += a1 * b3;
            acc[2][0] += a2 * b0; acc[2][1] += a2 * b1; acc[2][2] += a2 * b2; acc[2][3] += a2 * b3;
            acc[3][0] += a3 * b0; acc[3][1] += a3 * b1; acc[3][2] += a3 * b2; acc[3][3] += a3 * b3;
        }
        __syncthreads();
    }

#pragma unroll
    for (int i = 0; i < 4; i++) {
        int row = q0 + ty * 4 + i;
        float4 o = make_float4(acc[i][0] * SCALE, acc[i][1] * SCALE,
                               acc[i][2] * SCALE, acc[i][3] * SCALE);
        *(float4*)(Sc + (size_t)row * SEQ + k0v + tx * 4) = o;
    }
}

// ---------------------------------------------------------------------------
// Kernel 3: causal row softmax in place; writes explicit zeros for k > q.
// One block per (bh, q) row. Row cached in registers (<= 8 per thread).
// ---------------------------------------------------------------------------
__global__ __launch_bounds__(256) void softmax_kernel()
{
    const int row = blockIdx.x;            // bh*SEQ + q
    const int qpos = row & (SEQ - 1);
    float* p = g_scores + (size_t)row * SEQ;
    const int n = qpos + 1;
    const int t = threadIdx.x;

    __shared__ float red[8];

    float vals[8];
    int cnt = 0;
    float m = -INFINITY;
    for (int i = t; i < n; i += 256) {
        float v = p[i];
        vals[cnt++] = v;
        m = fmaxf(m, v);
    }
#pragma unroll
    for (int off = 16; off; off >>= 1) m = fmaxf(m, __shfl_xor_sync(0xffffffffu, m, off));
    if ((t & 31) == 0) red[t >> 5] = m;
    __syncthreads();
    if (t == 0) {
        float mm = red[0];
#pragma unroll
        for (int w = 1; w < 8; w++) mm = fmaxf(mm, red[w]);
        red[0] = mm;
    }
    __syncthreads();
    m = red[0];
    __syncthreads();

    float l = 0.f;
#pragma unroll
    for (int c = 0; c < 8; c++)
        if (c < cnt) { vals[c] = expf(vals[c] - m); l += vals[c]; }
#pragma unroll
    for (int off = 16; off; off >>= 1) l += __shfl_xor_sync(0xffffffffu, l, off);
    if ((t & 31) == 0) red[t >> 5] = l;
    __syncthreads();
    if (t == 0) {
        float s = 0.f;
#pragma unroll
        for (int w = 0; w < 8; w++) s += red[w];
        red[0] = s;
    }
    __syncthreads();
    const float inv = 1.0f / red[0];

    int c = 0;
    for (int i = t; i < SEQ; i += 256) {
        float o = 0.f;
        if (i < n) o = vals[c++] * inv;
        p[i] = o;
    }
}

// ---------------------------------------------------------------------------
// Kernel 4: O[s,d] = sum_z P[z,s] * V[z,d]   (transposed-P GEMM, per bh).
// P is zero for z < s, so z-loop starts at the m-tile base.
// ---------------------------------------------------------------------------
__global__ __launch_bounds__(256) void pv_kernel()
{
    const int nb = blockIdx.x;   // d tile (8)
    const int mb = blockIdx.y;   // s tile (32)
    const int bh = blockIdx.z;

    __shared__ float Az[32][68];   // [z][m]
    __shared__ float Bz[32][64];   // [z][d]

    const float* P = g_scores + (size_t)bh * SEQ * SEQ;
    const float* V = g_qkv + 2 * BHSD + (size_t)bh * SEQ * DIM;
    float* O = g_attn + (size_t)bh * SEQ * DIM;

    const int t = threadIdx.x, tx = t & 15, ty = t >> 4;
    const int m0 = mb * 64, n0 = nb * 64;
    const int la_r = t >> 4, la_c = (t & 15) * 4;

    float acc[4][4];
#pragma unroll
    for (int i = 0; i < 4; i++)
#pragma unroll
        for (int j = 0; j < 4; j++) acc[i][j] = 0.f;

    for (int k0 = m0; k0 < SEQ; k0 += 32) {
#pragma unroll
        for (int rep = 0; rep < 2; rep++) {
            int r = la_r + rep * 16;
            float4 v = *(const float4*)(P + (size_t)(k0 + r) * SEQ + m0 + la_c);
            *(float4*)&Az[r][la_c] = v;
            float4 w = *(const float4*)(V + (size_t)(k0 + r) * DIM + n0 + la_c);
            *(float4*)&Bz[r][la_c] = w;
        }
        __syncthreads();
#pragma unroll
        for (int kk = 0; kk < 32; kk++) {
            float a0 = Az[kk][ty * 4 + 0];
            float a1 = Az[kk][ty * 4 + 1];
            float a2 = Az[kk][ty * 4 + 2];
            float a3 = Az[kk][ty * 4 + 3];
            float4 bv = *(float4*)&Bz[kk][tx * 4];
            acc[0][0] += a0 * bv.x; acc[0][1] += a0 * bv.y; acc[0][2] += a0 * bv.z; acc[0][3] += a0 * bv.w;
            acc[1][0] += a1 * bv.x; acc[1][1] += a1 * bv.y; acc[1][2] += a1 * bv.z; acc[1][3] += a1 * bv.w;
            acc[2][0] += a2 * bv.x; acc[2][1] += a2 * bv.y; acc[2][2] += a2 * bv.z; acc[2][3] += a2 * bv.w;
            acc[3][0] += a3 * bv.x; acc[3][1] += a3 * bv.y; acc[3][2] += a3 * bv.z; acc[3][3] += a3 * bv.w;
        }
        __syncthreads();
    }

#pragma unroll
    for (int i = 0; i < 4; i++) {
        int m = m0 + ty * 4 + i;
        float4 o = make_float4(acc[i][0], acc[i][1], acc[i][2], acc[i][3]);
        *(float4*)(O + (size_t)m * DIM + n0 + tx * 4) = o;
    }
}

// ---------------------------------------------------------------------------
// Kernel 5: out[b,s,:] = concat_h(attn[b,h,s,:]) @ W_o   (M=4096,K=4096,N=512)
// ---------------------------------------------------------------------------
__global__ __launch_bounds__(256) void oproj_kernel(
    const float* __restrict__ Wo, float* __restrict__ out)
{
    __shared__ float As[64][33];
    __shared__ float Bs[32][64];

    const int t = threadIdx.x, tx = t & 15, ty = t >> 4;
    const int n0 = blockIdx.x * 64;
    const int m0 = blockIdx.y * 64;
    const int la_r = t >> 3, la_c = (t & 7) * 4;
    const int lb_r = t >> 4, lb_c = (t & 15) * 4;

    float acc[4][4];
#pragma unroll
    for (int i = 0; i < 4; i++)
#pragma unroll
        for (int j = 0; j < 4; j++) acc[i][j] = 0.f;

    for (int k0 = 0; k0 < NH * DIM; k0 += 32) {
        const int h  = k0 >> 9;      // uniform within the 32-wide k tile
        const int d0 = k0 & 511;
#pragma unroll
        for (int rep = 0; rep < 2; rep++) {
            int r = la_r + rep * 32;
            int m = m0 + r;
            int bb = m >> 11, s = m & (SEQ - 1);
            float4 v = *(const float4*)(g_attn + (((size_t)(bb * NH + h)) * SEQ + s) * DIM + d0 + la_c);
            As[r][la_c + 0] = v.x; As[r][la_c + 1] = v.y;
            As[r][la_c + 2] = v.z; As[r][la_c + 3] = v.w;
        }
#pragma unroll
        for (int rep = 0; rep < 2; rep++) {
            int r = lb_r + rep * 16;
            float4 v = *(const float4*)(Wo + (size_t)(k0 + r) * DIM + n0 + lb_c);
            *(float4*)&Bs[r][lb_c] = v;
        }
        __syncthreads();
#pragma unroll
        for (int kk = 0; kk < 32; kk++) {
            float a0 = As[ty * 4 + 0][kk];
            float a1 = As[ty * 4 + 1][kk];
            float a2 = As[ty * 4 + 2][kk];
            float a3 = As[ty * 4 + 3][kk];
            float4 bv = *(float4*)&Bs[kk][tx * 4];
            acc[0][0] += a0 * bv.x; acc[0][1] += a0 * bv.y; acc[0][2] += a0 * bv.z; acc[0][3] += a0 * bv.w;
            acc[1][0] += a1 * bv.x; acc[1][1] += a1 * bv.y; acc[1][2] += a1 * bv.z; acc[1][3] += a1 * bv.w;
            acc[2][0] += a2 * bv.x; acc[2][1] += a2 * bv.y; acc[2][2] += a2 * bv.z; acc[2][3] += a2 * bv.w;
            acc[3][0] += a3 * bv.x; acc[3][1] += a3 * bv.y; acc[3][2] += a3 * bv.z; acc[3][3] += a3 * bv.w;
        }
        __syncthreads();
    }

#pragma unroll
    for (int i = 0; i < 4; i++) {
        int m = m0 + ty * 4 + i;
        float4 o = make_float4(acc[i][0], acc[i][1], acc[i][2], acc[i][3]);
        *(float4*)(out + (size_t)m * DIM + n0 + tx * 4) = o;
    }
}

// ---------------------------------------------------------------------------
extern "C" void kernel_launch(void* const* d_in, const int* in_sizes, int n_in,
                              void* d_out, int out_size)
{
    const float* q  = (const float*)d_in[0];
    const float* Wq = (const float*)d_in[1];
    const float* Wk = (const float*)d_in[2];
    const float* Wv = (const float*)d_in[3];
    const float* Wo = (const float*)d_in[4];
    float* out = (float*)d_out;

    proj_kernel<<<dim3(8, 64, 24), 256>>>(q, Wq, Wk, Wv);
    scores_kernel<<<dim3(32, 32, BHN), 256>>>();
    softmax_kernel<<<BHN * SEQ, 256>>>();
    pv_kernel<<<dim3(8, 32, BHN), 256>>>();
    oproj_kernel<<<dim3(8, 64), 256>>>(Wo, out);
}

// round 4
// speedup vs baseline: 2.2063x; 2.2063x over previous
#include <cuda_runtime.h>
#include <math.h>
#include <stdint.h>

#define BATCH 2
#define SEQ   2048
#define DIM   512
#define NH    8
#define BHN   16
#define SD    (SEQ*DIM)
#define SS    (SEQ*SEQ)
#define BHSD  16777216ULL
#define SCALE 0.04419417382415922f
#define RFREQ (-0.025952563241307517f)   // -log2(10000)/512

// ---------------- scratch (device globals; no runtime alloc) ----------------
__device__ float g_qkv[50331648];    // [3][bh][s][d]
__device__ float g_scores[67108864]; // [bh][q][k]  scores -> probs in place
__device__ float g_attn[16777216];   // [bh][s][d]
__device__ float g_pt[67108864];     // [bh][s][z] = P^T
__device__ float g_vt[16777216];     // [bh][d][z] = V^T
__device__ float g_wt[6291456];      // [which*8+h][d][z]  (W^T: B K-major)
__device__ float g_wot[2097152];     // [d][k]             (Wo^T)

#define PITCH 20                       // floats per smem row (16 data + 4 pad)
#define ASZ   (128*PITCH)              // floats per stage

__device__ __forceinline__ void cp16(void* sdst, const void* gsrc) {
    uint32_t sa = (uint32_t)__cvta_generic_to_shared(sdst);
    asm volatile("cp.async.cg.shared.global [%0], [%1], 16;" :: "r"(sa), "l"(gsrc));
}
__device__ __forceinline__ void cp_commit() { asm volatile("cp.async.commit_group;"); }
template<int N> __device__ __forceinline__ void cp_wait() {
    asm volatile("cp.async.wait_group %0;" :: "n"(N));
}
__device__ __forceinline__ void mma8(float* c, const uint32_t* a, const uint32_t* b) {
    asm volatile("mma.sync.aligned.m16n8k8.row.col.f32.tf32.tf32.f32 "
        "{%0,%1,%2,%3}, {%4,%5,%6,%7}, {%8,%9}, {%0,%1,%2,%3};"
        : "+f"(c[0]), "+f"(c[1]), "+f"(c[2]), "+f"(c[3])
        : "r"(a[0]), "r"(a[1]), "r"(a[2]), "r"(a[3]), "r"(b[0]), "r"(b[1]));
}
__device__ __forceinline__ uint32_t tf32_hi(float x) {
    float y;
    asm("cvt.rna.tf32.f32 %0, %1;" : "=f"(y) : "f"(x));
    return __float_as_uint(y);
}

// ---------------------------------------------------------------------------
// Unified 3xTF32 mma.sync GEMM. KIND: 0=proj(+RoPE), 1=scores, 2=PV, 3=oproj
// CTA computes C[128,128]; A[m][k], B[n][k] both K-major in gmem.
// ---------------------------------------------------------------------------
template<int KIND>
__global__ __launch_bounds__(256, 2) void mma_kernel(const float* __restrict__ qin,
                                                     float* __restrict__ cout)
{
    int m0, n0, kstart, kend;
    const float *Ab = nullptr, *Bb = nullptr;
    size_t lda = 0, ldb = 0;
    int h = 0, which = 0, bh = 0;

    if constexpr (KIND == 0) {
        which = blockIdx.z >> 3; h = blockIdx.z & 7;
        m0 = blockIdx.y * 128; n0 = blockIdx.x * 128; kstart = 0; kend = 512;
        Ab = qin; lda = 512;
        Bb = g_wt + (size_t)(which * 8 + h) * 262144; ldb = 512;
    } else if constexpr (KIND == 1) {
        if (blockIdx.x > blockIdx.y) return;
        bh = blockIdx.z;
        m0 = blockIdx.y * 128; n0 = blockIdx.x * 128; kstart = 0; kend = 512;
        Ab = g_qkv + (size_t)bh * SD; lda = 512;
        Bb = g_qkv + BHSD + (size_t)bh * SD; ldb = 512;
    } else if constexpr (KIND == 2) {
        bh = blockIdx.z;
        m0 = blockIdx.y * 128; n0 = blockIdx.x * 128; kstart = m0; kend = SEQ;
        Ab = g_pt + (size_t)bh * SS; lda = SEQ;
        Bb = g_vt + (size_t)bh * SD; ldb = SEQ;
    } else {
        m0 = blockIdx.y * 128; n0 = blockIdx.x * 128; kstart = 0; kend = 4096;
        Bb = g_wot; ldb = 4096;
    }

    __shared__ float smA[2][ASZ];
    __shared__ float smB[2][ASZ];

    const int tid = threadIdx.x;
    const int wid = tid >> 5, lane = tid & 31;
    const int mw = (wid >> 2) * 64, nw = (wid & 3) * 32;
    const int lr = lane >> 2, lc = lane & 3;

    float acc[4][4][4];
#pragma unroll
    for (int a = 0; a < 4; a++)
#pragma unroll
        for (int b = 0; b < 4; b++)
#pragma unroll
            for (int c = 0; c < 4; c++) acc[a][b][c] = 0.f;

    const int nStages = (kend - kstart) >> 4;

    // stage loader: 128 rows x 16 floats per operand = 512 16B chunks; 2/thread
    auto load_stage = [&](int s, int buf) {
        const int k0 = kstart + (s << 4);
#pragma unroll
        for (int j = 0; j < 2; j++) {
            const int ci = tid + (j << 8);
            const int row = ci >> 2, cc4 = (ci & 3) * 4;
            const float* ga;
            if constexpr (KIND == 3) {
                const int m = m0 + row, k = k0 + cc4;
                ga = g_attn + (((size_t)((m >> 11) * 8 + (k >> 9))) * SEQ + (m & (SEQ - 1))) * 512 + (k & 511);
            } else {
                ga = Ab + (size_t)(m0 + row) * lda + k0 + cc4;
            }
            cp16(&smA[buf][row * PITCH + cc4], ga);
            cp16(&smB[buf][row * PITCH + cc4], Bb + (size_t)(n0 + row) * ldb + k0 + cc4);
        }
        cp_commit();
    };

    load_stage(0, 0);

    for (int s = 0; s < nStages; s++) {
        const int buf = s & 1;
        if (s + 1 < nStages) { load_stage(s + 1, buf ^ 1); cp_wait<1>(); }
        else                 { cp_wait<0>(); }
        __syncthreads();

        const float* As = smA[buf];
        const float* Bs = smB[buf];
#pragma unroll
        for (int k8 = 0; k8 < 16; k8 += 8) {
            // B fragments: split hi/lo once per k8
            uint32_t bh_[4][2], bl_[4][2];
#pragma unroll
            for (int nt = 0; nt < 4; nt++) {
                const float* p = Bs + (nw + nt * 8 + lr) * PITCH + k8 + lc;
#pragma unroll
                for (int j = 0; j < 2; j++) {
                    float v = p[j * 4];
                    uint32_t hi = tf32_hi(v);
                    bh_[nt][j] = hi;
                    bl_[nt][j] = tf32_hi(v - __uint_as_float(hi));
                }
            }
#pragma unroll
            for (int mt = 0; mt < 4; mt++) {
                const float* p = As + (mw + mt * 16 + lr) * PITCH + k8 + lc;
                float av[4];
                av[0] = p[0];
                av[1] = p[8 * PITCH];
                av[2] = p[4];
                av[3] = p[8 * PITCH + 4];
                uint32_t ah[4], al[4];
#pragma unroll
                for (int j = 0; j < 4; j++) {
                    uint32_t hi = tf32_hi(av[j]);
                    ah[j] = hi;
                    al[j] = tf32_hi(av[j] - __uint_as_float(hi));
                }
#pragma unroll
                for (int nt = 0; nt < 4; nt++) {
                    mma8(acc[mt][nt], al, bh_[nt]);
                    mma8(acc[mt][nt], ah, bl_[nt]);
                    mma8(acc[mt][nt], ah, bh_[nt]);
                }
            }
        }
        __syncthreads();
    }

    // -------- epilogue (fragment c0,c1 -> (row, col..col+1); c2,c3 -> row+8) --
#pragma unroll
    for (int mt = 0; mt < 4; mt++) {
#pragma unroll
        for (int nt = 0; nt < 4; nt++) {
            float* cc = acc[mt][nt];
            const int gr = m0 + mw + mt * 16 + lr;
            const int gc = n0 + nw + nt * 8 + lc * 2;
#pragma unroll
            for (int half = 0; half < 2; half++) {
                const int r = gr + half * 8;
                float v0 = cc[half * 2], v1 = cc[half * 2 + 1];
                if constexpr (KIND == 0) {
                    const int bb = r >> 11, ss = r & (SEQ - 1);
                    if (which < 2) {
                        float inv = exp2f((float)gc * RFREQ);
                        float ang = (float)ss * inv, sn, cs;
                        sincosf(ang, &sn, &cs);
                        float x1 = v0, x2 = v1;
                        v0 = x1 * cs - x2 * sn;
                        v1 = x1 * sn + x2 * cs;
                    }
                    *(float2*)(g_qkv + (size_t)which * BHSD +
                               (((size_t)(bb * 8 + h)) * SEQ + ss) * 512 + gc) = make_float2(v0, v1);
                } else if constexpr (KIND == 1) {
                    *(float2*)(g_scores + (size_t)bh * SS + (size_t)r * SEQ + gc) =
                        make_float2(v0 * SCALE, v1 * SCALE);
                } else if constexpr (KIND == 2) {
                    *(float2*)(g_attn + (size_t)bh * SD + (size_t)r * 512 + gc) = make_float2(v0, v1);
                } else {
                    *(float2*)(cout + (size_t)r * 512 + gc) = make_float2(v0, v1);
                }
            }
        }
    }
}

// ---------------------------------------------------------------------------
// Tiled transpose. MODE: 0..2 W_{q,k,v}->g_wt, 3 Wo->g_wot, 4 V->g_vt, 5 P->g_pt
// ---------------------------------------------------------------------------
template<int MODE>
__global__ void transpose_kernel(const float* __restrict__ ext)
{
    __shared__ float t[32][33];
    int rows, cols;
    const float* s; float* d;
    if constexpr (MODE <= 2) {
        rows = 512; cols = 512;
        s = ext + (size_t)blockIdx.z * 262144;
        d = g_wt + (size_t)(MODE * 8 + blockIdx.z) * 262144;
    } else if constexpr (MODE == 3) {
        rows = 4096; cols = 512; s = ext; d = g_wot;
    } else if constexpr (MODE == 4) {
        rows = SEQ; cols = 512;
        s = g_qkv + 2 * BHSD + (size_t)blockIdx.z * SD;
        d = g_vt + (size_t)blockIdx.z * SD;
    } else {
        rows = SEQ; cols = SEQ;
        s = g_scores + (size_t)blockIdx.z * SS;
        d = g_pt + (size_t)blockIdx.z * SS;
    }
    const int tx = threadIdx.x, ty = threadIdx.y;
    const int xs = blockIdx.x * 32 + tx;
    const int ys = blockIdx.y * 32;
#pragma unroll
    for (int i = ty; i < 32; i += 8) t[i][tx] = s[(size_t)(ys + i) * cols + xs];
    __syncthreads();
    const int xd = blockIdx.y * 32 + tx;
#pragma unroll
    for (int i = ty; i < 32; i += 8)
        d[(size_t)(blockIdx.x * 32 + i) * rows + xd] = t[tx][i];
}

// ---------------------------------------------------------------------------
// Causal row softmax in place (writes explicit zeros for k > q).
// ---------------------------------------------------------------------------
__global__ __launch_bounds__(256) void softmax_kernel()
{
    const int row = blockIdx.x;
    const int qpos = row & (SEQ - 1);
    float* p = g_scores + (size_t)row * SEQ;
    const int n = qpos + 1;
    const int t = threadIdx.x;
    __shared__ float red[8];

    float vals[8];
    int cnt = 0;
    float m = -INFINITY;
    for (int i = t; i < n; i += 256) { float v = p[i]; vals[cnt++] = v; m = fmaxf(m, v); }
#pragma unroll
    for (int off = 16; off; off >>= 1) m = fmaxf(m, __shfl_xor_sync(0xffffffffu, m, off));
    if ((t & 31) == 0) red[t >> 5] = m;
    __syncthreads();
    if (t == 0) { float mm = red[0];
#pragma unroll
        for (int w = 1; w < 8; w++) mm = fmaxf(mm, red[w]); red[0] = mm; }
    __syncthreads();
    m = red[0];
    __syncthreads();

    float l = 0.f;
#pragma unroll
    for (int c = 0; c < 8; c++) if (c < cnt) { vals[c] = expf(vals[c] - m); l += vals[c]; }
#pragma unroll
    for (int off = 16; off; off >>= 1) l += __shfl_xor_sync(0xffffffffu, l, off);
    if ((t & 31) == 0) red[t >> 5] = l;
    __syncthreads();
    if (t == 0) { float ss = 0.f;
#pragma unroll
        for (int w = 0; w < 8; w++) ss += red[w]; red[0] = ss; }
    __syncthreads();
    const float inv = 1.0f / red[0];

    int c = 0;
    for (int i = t; i < SEQ; i += 256) {
        float o = 0.f;
        if (i < n) o = vals[c++] * inv;
        p[i] = o;
    }
}

// ---------------------------------------------------------------------------
extern "C" void kernel_launch(void* const* d_in, const int* in_sizes, int n_in,
                              void* d_out, int out_size)
{
    const float* q  = (const float*)d_in[0];
    const float* Wq = (const float*)d_in[1];
    const float* Wk = (const float*)d_in[2];
    const float* Wv = (const float*)d_in[3];
    const float* Wo = (const float*)d_in[4];
    float* out = (float*)d_out;

    dim3 tb(32, 8);
    transpose_kernel<0><<<dim3(16, 16, 8), tb>>>(Wq);
    transpose_kernel<1><<<dim3(16, 16, 8), tb>>>(Wk);
    transpose_kernel<2><<<dim3(16, 16, 8), tb>>>(Wv);
    transpose_kernel<3><<<dim3(16, 128, 1), tb>>>(Wo);

    mma_kernel<0><<<dim3(4, 32, 24), 256>>>(q, nullptr);        // QKV proj + RoPE
    transpose_kernel<4><<<dim3(16, 64, 16), tb>>>(nullptr);     // V -> V^T
    mma_kernel<1><<<dim3(16, 16, 16), 256>>>(nullptr, nullptr); // scores (causal tiles)
    softmax_kernel<<<BHN * SEQ, 256>>>();
    transpose_kernel<5><<<dim3(64, 64, 16), tb>>>(nullptr);     // P -> P^T
    mma_kernel<2><<<dim3(4, 16, 16), 256>>>(nullptr, nullptr);  // O = P^T V
    mma_kernel<3><<<dim3(4, 32, 1), 256>>>(nullptr, out);       // out proj
}

// round 5
// speedup vs baseline: 3.5006x; 1.5866x over previous
#include <cuda_runtime.h>
#include <math.h>
#include <stdint.h>

#define BATCH 2
#define SEQ   2048
#define DIM   512
#define NH    8
#define BHN   16
#define SD    (SEQ*DIM)
#define SS    (SEQ*SEQ)
#define BHSD  16777216ULL
#define SCALE 0.04419417382415922f
#define RFREQ (-0.025952563241307517f)   // -log2(10000)/512

// ---------------- scratch (device globals; no runtime alloc) ----------------
__device__ float g_qkv[50331648];    // [3][bh][s][d]
__device__ float g_scores[67108864]; // [bh][q][k]  scores -> probs in place
__device__ float g_attn[16777216];   // [bh][s][d]

#define PITCH0 20                      // K-major staging: [128 rows][16 k] + pad
#define PITCH1 132                     // MN-major staging: [16 k][128 mn] + pad
#define STAGEF 2560                    // max floats per stage (128*20 > 16*132)

__device__ __forceinline__ void cp16(void* sdst, const void* gsrc) {
    uint32_t sa = (uint32_t)__cvta_generic_to_shared(sdst);
    asm volatile("cp.async.cg.shared.global [%0], [%1], 16;" :: "r"(sa), "l"(gsrc));
}
__device__ __forceinline__ void cp_commit() { asm volatile("cp.async.commit_group;"); }
template<int N> __device__ __forceinline__ void cp_wait() {
    asm volatile("cp.async.wait_group %0;" :: "n"(N));
}
// D += A*B, bf16 m16n8k16
__device__ __forceinline__ void mma16(float* c, const uint32_t* a, const uint32_t* b) {
    asm volatile("mma.sync.aligned.m16n8k16.row.col.f32.bf16.bf16.f32 "
        "{%0,%1,%2,%3}, {%4,%5,%6,%7}, {%8,%9}, {%0,%1,%2,%3};"
        : "+f"(c[0]), "+f"(c[1]), "+f"(c[2]), "+f"(c[3])
        : "r"(a[0]), "r"(a[1]), "r"(a[2]), "r"(a[3]), "r"(b[0]), "r"(b[1]));
}
// pack {x0 -> low, x1 -> high} as bf16x2 hi + residual lo
__device__ __forceinline__ void split2(float x0, float x1, uint32_t& hi, uint32_t& lo) {
    uint32_t h;
    asm("cvt.rn.bf16x2.f32 %0, %1, %2;" : "=r"(h) : "f"(x1), "f"(x0));
    hi = h;
    float h0 = __uint_as_float(h << 16);
    float h1 = __uint_as_float(h & 0xFFFF0000u);
    float r0 = x0 - h0, r1 = x1 - h1;
    asm("cvt.rn.bf16x2.f32 %0, %1, %2;" : "=r"(lo) : "f"(r1), "f"(r0));
}

// ---------------------------------------------------------------------------
// Unified bf16-split mma.sync GEMM. KIND: 0=proj(+RoPE), 1=scores, 2=PV, 3=oproj
// C[128,128] per CTA. Operand orientation:
//   orient0: gmem K-major [mn][k] (Q, K, attn-gather)  -> stage [128 mn][16 k]
//   orient1: gmem MN-major [k][mn] (W, Wo, V, P)       -> stage [16 k][128 mn]
// ---------------------------------------------------------------------------
template<int KIND>
__global__ __launch_bounds__(256, 2) void mma_kernel(
    const float* __restrict__ qin, const float* __restrict__ w0,
    const float* __restrict__ w1, const float* __restrict__ w2,
    float* __restrict__ cout)
{
    constexpr int AOR = (KIND == 2) ? 1 : 0;
    constexpr int BOR = (KIND == 1) ? 0 : 1;

    int m0, n0, kstart, kend;
    const float *Ab = nullptr, *Bb = nullptr;
    size_t lda = 0, ldb = 0;
    int h = 0, which = 0, bh = 0;

    if constexpr (KIND == 0) {
        which = blockIdx.z >> 3; h = blockIdx.z & 7;
        m0 = blockIdx.y * 128; n0 = blockIdx.x * 128; kstart = 0; kend = 512;
        Ab = qin; lda = 512;
        Bb = (which == 0 ? w0 : (which == 1 ? w1 : w2)) + (size_t)h * 262144; ldb = 512;
    } else if constexpr (KIND == 1) {
        if (blockIdx.x > blockIdx.y) return;
        bh = blockIdx.z;
        m0 = blockIdx.y * 128; n0 = blockIdx.x * 128; kstart = 0; kend = 512;
        Ab = g_qkv + (size_t)bh * SD; lda = 512;
        Bb = g_qkv + BHSD + (size_t)bh * SD; ldb = 512;
    } else if constexpr (KIND == 2) {
        bh = blockIdx.z;
        m0 = blockIdx.y * 128; n0 = blockIdx.x * 128; kstart = m0; kend = SEQ;
        Ab = g_scores + (size_t)bh * SS; lda = SEQ;          // P[z][s], MN-major
        Bb = g_qkv + 2 * BHSD + (size_t)bh * SD; ldb = 512;  // V[z][d], MN-major
    } else {
        m0 = blockIdx.y * 128; n0 = blockIdx.x * 128; kstart = 0; kend = 4096;
        Bb = w0; ldb = 512;                                   // Wo[k][n], MN-major
    }

    __shared__ float smA[2][STAGEF];
    __shared__ float smB[2][STAGEF];

    const int tid = threadIdx.x;
    const int wid = tid >> 5, lane = tid & 31;
    const int mw = (wid >> 2) * 64, nw = (wid & 3) * 32;
    const int g = lane >> 2, t = lane & 3;   // groupID, thread-in-group

    float acc[4][4][4];
#pragma unroll
    for (int a = 0; a < 4; a++)
#pragma unroll
        for (int b = 0; b < 4; b++)
#pragma unroll
            for (int c = 0; c < 4; c++) acc[a][b][c] = 0.f;

    const int nStages = (kend - kstart) >> 4;

    auto load_stage = [&](int s, int buf) {
        const int k0 = kstart + (s << 4);
        // ---- A ----
        if constexpr (AOR == 0) {
#pragma unroll
            for (int j = 0; j < 2; j++) {
                const int ci = tid + (j << 8);
                const int row = ci >> 2, c4 = (ci & 3) * 4;
                const float* ga;
                if constexpr (KIND == 3) {
                    const int m = m0 + row, k = k0 + c4;
                    ga = g_attn + (((size_t)((m >> 11) * 8 + (k >> 9))) * SEQ + (m & (SEQ - 1))) * 512 + (k & 511);
                } else {
                    ga = Ab + (size_t)(m0 + row) * lda + k0 + c4;
                }
                cp16(&smA[buf][row * PITCH0 + c4], ga);
            }
        } else {
#pragma unroll
            for (int j = 0; j < 2; j++) {
                const int ci = tid + (j << 8);
                const int row = ci >> 5, c4 = (ci & 31) * 4;
                cp16(&smA[buf][row * PITCH1 + c4], Ab + (size_t)(k0 + row) * lda + m0 + c4);
            }
        }
        // ---- B ----
        if constexpr (BOR == 0) {
#pragma unroll
            for (int j = 0; j < 2; j++) {
                const int ci = tid + (j << 8);
                const int row = ci >> 2, c4 = (ci & 3) * 4;
                cp16(&smB[buf][row * PITCH0 + c4], Bb + (size_t)(n0 + row) * ldb + k0 + c4);
            }
        } else {
#pragma unroll
            for (int j = 0; j < 2; j++) {
                const int ci = tid + (j << 8);
                const int row = ci >> 5, c4 = (ci & 31) * 4;
                cp16(&smB[buf][row * PITCH1 + c4], Bb + (size_t)(k0 + row) * ldb + n0 + c4);
            }
        }
        cp_commit();
    };

    load_stage(0, 0);

    for (int s = 0; s < nStages; s++) {
        const int buf = s & 1;
        if (s + 1 < nStages) { load_stage(s + 1, buf ^ 1); cp_wait<1>(); }
        else                 { cp_wait<0>(); }
        __syncthreads();

        const float* As = smA[buf];
        const float* Bs = smB[buf];

        // B fragments (split once per stage)
        uint32_t bhf[4][2], blf[4][2];
#pragma unroll
        for (int nt = 0; nt < 4; nt++) {
            const int nn = nw + nt * 8 + g;
            float x0, x1, y0, y1;
            if constexpr (BOR == 0) {
                float2 p = *(const float2*)&Bs[nn * PITCH0 + 2 * t];
                float2 q2 = *(const float2*)&Bs[nn * PITCH0 + 2 * t + 8];
                x0 = p.x; x1 = p.y; y0 = q2.x; y1 = q2.y;
            } else {
                x0 = Bs[(2 * t) * PITCH1 + nn];
                x1 = Bs[(2 * t + 1) * PITCH1 + nn];
                y0 = Bs[(2 * t + 8) * PITCH1 + nn];
                y1 = Bs[(2 * t + 9) * PITCH1 + nn];
            }
            split2(x0, x1, bhf[nt][0], blf[nt][0]);
            split2(y0, y1, bhf[nt][1], blf[nt][1]);
        }

#pragma unroll
        for (int mt = 0; mt < 4; mt++) {
            const int rm = mw + mt * 16 + g;
            float v[8];
            if constexpr (AOR == 0) {
                float2 p0 = *(const float2*)&As[rm * PITCH0 + 2 * t];
                float2 p1 = *(const float2*)&As[(rm + 8) * PITCH0 + 2 * t];
                float2 p2 = *(const float2*)&As[rm * PITCH0 + 2 * t + 8];
                float2 p3 = *(const float2*)&As[(rm + 8) * PITCH0 + 2 * t + 8];
                v[0] = p0.x; v[1] = p0.y; v[2] = p1.x; v[3] = p1.y;
                v[4] = p2.x; v[5] = p2.y; v[6] = p3.x; v[7] = p3.y;
            } else {
                v[0] = As[(2 * t) * PITCH1 + rm];
                v[1] = As[(2 * t + 1) * PITCH1 + rm];
                v[2] = As[(2 * t) * PITCH1 + rm + 8];
                v[3] = As[(2 * t + 1) * PITCH1 + rm + 8];
                v[4] = As[(2 * t + 8) * PITCH1 + rm];
                v[5] = As[(2 * t + 9) * PITCH1 + rm];
                v[6] = As[(2 * t + 8) * PITCH1 + rm + 8];
                v[7] = As[(2 * t + 9) * PITCH1 + rm + 8];
            }
            uint32_t ah[4], al[4];
            split2(v[0], v[1], ah[0], al[0]);   // a0: row rm,   k 2t,2t+1
            split2(v[2], v[3], ah[1], al[1]);   // a1: row rm+8
            split2(v[4], v[5], ah[2], al[2]);   // a2: row rm,   k 2t+8,2t+9
            split2(v[6], v[7], ah[3], al[3]);   // a3: row rm+8
#pragma unroll
            for (int nt = 0; nt < 4; nt++) {
                mma16(acc[mt][nt], al, bhf[nt]);
                mma16(acc[mt][nt], ah, blf[nt]);
                mma16(acc[mt][nt], ah, bhf[nt]);
            }
        }
        __syncthreads();
    }

    // -------- epilogue: c0,c1 -> (row g, col 2t,2t+1); c2,c3 -> row g+8 -----
#pragma unroll
    for (int mt = 0; mt < 4; mt++) {
#pragma unroll
        for (int nt = 0; nt < 4; nt++) {
            float* cc = acc[mt][nt];
            const int gr = m0 + mw + mt * 16 + g;
            const int gc = n0 + nw + nt * 8 + t * 2;
#pragma unroll
            for (int half = 0; half < 2; half++) {
                const int r = gr + half * 8;
                float v0 = cc[half * 2], v1 = cc[half * 2 + 1];
                if constexpr (KIND == 0) {
                    const int bb = r >> 11, ss = r & (SEQ - 1);
                    if (which < 2) {
                        float inv = exp2f((float)gc * RFREQ);
                        float ang = (float)ss * inv, sn, cs;
                        sincosf(ang, &sn, &cs);
                        float x1 = v0, x2 = v1;
                        v0 = x1 * cs - x2 * sn;
                        v1 = x1 * sn + x2 * cs;
                    }
                    *(float2*)(g_qkv + (size_t)which * BHSD +
                               (((size_t)(bb * 8 + h)) * SEQ + ss) * 512 + gc) = make_float2(v0, v1);
                } else if constexpr (KIND == 1) {
                    *(float2*)(g_scores + (size_t)bh * SS + (size_t)r * SEQ + gc) =
                        make_float2(v0 * SCALE, v1 * SCALE);
                } else if constexpr (KIND == 2) {
                    *(float2*)(g_attn + (size_t)bh * SD + (size_t)r * 512 + gc) = make_float2(v0, v1);
                } else {
                    *(float2*)(cout + (size_t)r * 512 + gc) = make_float2(v0, v1);
                }
            }
        }
    }
}

// ---------------------------------------------------------------------------
// Causal row softmax in place (writes explicit zeros for k > q).
// ---------------------------------------------------------------------------
__global__ __launch_bounds__(256) void softmax_kernel()
{
    const int row = blockIdx.x;
    const int qpos = row & (SEQ - 1);
    float* p = g_scores + (size_t)row * SEQ;
    const int n = qpos + 1;
    const int t = threadIdx.x;
    __shared__ float red[8];

    float vals[8];
    int cnt = 0;
    float m = -INFINITY;
    for (int i = t; i < n; i += 256) { float v = p[i]; vals[cnt++] = v; m = fmaxf(m, v); }
#pragma unroll
    for (int off = 16; off; off >>= 1) m = fmaxf(m, __shfl_xor_sync(0xffffffffu, m, off));
    if ((t & 31) == 0) red[t >> 5] = m;
    __syncthreads();
    if (t == 0) { float mm = red[0];
#pragma unroll
        for (int w = 1; w < 8; w++) mm = fmaxf(mm, red[w]); red[0] = mm; }
    __syncthreads();
    m = red[0];
    __syncthreads();

    float l = 0.f;
#pragma unroll
    for (int c = 0; c < 8; c++) if (c < cnt) { vals[c] = expf(vals[c] - m); l += vals[c]; }
#pragma unroll
    for (int off = 16; off; off >>= 1) l += __shfl_xor_sync(0xffffffffu, l, off);
    if ((t & 31) == 0) red[t >> 5] = l;
    __syncthreads();
    if (t == 0) { float ss = 0.f;
#pragma unroll
        for (int w = 0; w < 8; w++) ss += red[w]; red[0] = ss; }
    __syncthreads();
    const float inv = 1.0f / red[0];

    int c = 0;
    for (int i = t; i < SEQ; i += 256) {
        float o = 0.f;
        if (i < n) o = vals[c++] * inv;
        p[i] = o;
    }
}

// ---------------------------------------------------------------------------
extern "C" void kernel_launch(void* const* d_in, const int* in_sizes, int n_in,
                              void* d_out, int out_size)
{
    const float* q  = (const float*)d_in[0];
    const float* Wq = (const float*)d_in[1];
    const float* Wk = (const float*)d_in[2];
    const float* Wv = (const float*)d_in[3];
    const float* Wo = (const float*)d_in[4];
    float* out = (float*)d_out;

    mma_kernel<0><<<dim3(4, 32, 24), 256>>>(q, Wq, Wk, Wv, nullptr);          // QKV proj + RoPE
    mma_kernel<1><<<dim3(16, 16, 16), 256>>>(nullptr, nullptr, nullptr, nullptr, nullptr); // scores
    softmax_kernel<<<BHN * SEQ, 256>>>();
    mma_kernel<2><<<dim3(4, 16, 16), 256>>>(nullptr, nullptr, nullptr, nullptr, nullptr);  // O = P^T V
    mma_kernel<3><<<dim3(4, 32, 1), 256>>>(nullptr, Wo, nullptr, nullptr, out);            // out proj
}